// round 1
// baseline (speedup 1.0000x reference)
#include <cuda_runtime.h>
#include <cstdint>

// Problem constants
constexpr int V_ = 20000;
constexpr int E_ = 300;
constexpr int H_ = 2400;
constexpr int B_ = 32;
constexpr int S_ = 64;
constexpr int M_ = B_ * S_;   // 2048 sequence-flattened rows
constexpr int G_ = 3 * H_;    // 7200 gate width

// Scratch (static device allocations are allowed; cudaMalloc is not)
__device__ float g_emb[M_ * E_];            // 2.4 MB  gathered embeddings
__device__ float g_xg[M_ * G_];             // 59 MB   input-side gate preacts
__device__ float g_hs[M_ * H_];             // 19.7 MB hidden states per step
__device__ float g_hg[B_ * G_];             // 0.9 MB  recurrent gate preacts
__device__ float g_h0[B_ * H_];             // hidden double-buffer
__device__ float g_h1[B_ * H_];

// ---------------------------------------------------------------------------
// tf32 helpers
// ---------------------------------------------------------------------------
__device__ __forceinline__ uint32_t f2tf32(float x) {
    uint32_t u;
    asm("cvt.rna.tf32.f32 %0, %1;" : "=r"(u) : "f"(x));
    return u;
}

#define MMA_TF32(c, a, b)                                                     \
    asm volatile(                                                             \
        "mma.sync.aligned.m16n8k8.row.col.f32.tf32.tf32.f32 "                 \
        "{%0,%1,%2,%3}, {%4,%5,%6,%7}, {%8,%9}, {%0,%1,%2,%3};\n"             \
        : "+f"((c)[0]), "+f"((c)[1]), "+f"((c)[2]), "+f"((c)[3])              \
        : "r"((a)[0]), "r"((a)[1]), "r"((a)[2]), "r"((a)[3]),                 \
          "r"((b)[0]), "r"((b)[1]))

// ---------------------------------------------------------------------------
// Embedding gather + h0 init
// ---------------------------------------------------------------------------
__global__ void gather_init_kernel(const int* __restrict__ tgt,
                                   const float* __restrict__ emb_table,
                                   const float* __restrict__ sentence_vec) {
    int idx = blockIdx.x * blockDim.x + threadIdx.x;
    if (idx < M_ * E_) {
        int m = idx / E_;
        int e = idx - m * E_;
        g_emb[idx] = emb_table[(size_t)tgt[m] * E_ + e];
    }
    if (idx < B_ * H_) {
        g_h0[idx] = sentence_vec[idx];
    }
}

// ---------------------------------------------------------------------------
// Generic tf32 GEMM: C[m,n] = sum_k A[m,k]*B[n,k] + bias[n]
// A: [M,K] row-major f32   B: [N,K] row-major f32   C: [M,N] f32
// Requires M % BM == 0. N, K arbitrary (guarded).
// ---------------------------------------------------------------------------
template <int BM, int BN, int BK, int WM, int WN>
__global__ void __launch_bounds__(256)
gemm_tf32_kernel(const float* __restrict__ A, const float* __restrict__ Bm,
                 const float* __restrict__ bias, float* __restrict__ C,
                 int M, int N, int K) {
    constexpr int WARPS_M = BM / WM;
    constexpr int WARPS_N = BN / WN;
    constexpr int NTHREADS = WARPS_M * WARPS_N * 32;
    constexpr int MFRAG = WM / 16;
    constexpr int NFRAG = WN / 8;
    constexpr int PAD = 4;
    static_assert(NTHREADS == 256, "tile config must use 256 threads");

    __shared__ float As[BK][BM + PAD];
    __shared__ float Bs[BK][BN + PAD];

    const int tid = threadIdx.x;
    const int warp = tid >> 5;
    const int lane = tid & 31;
    const int gr = lane >> 2;  // group id   (0..7)
    const int gc = lane & 3;   // thread-in-group (0..3)

    const int wm = (warp % WARPS_M) * WM;
    const int wn = (warp / WARPS_M) * WN;
    const int bm0 = blockIdx.x * BM;   // m-tiles on x: consecutive CTAs share B tile via L2
    const int bn0 = blockIdx.y * BN;

    float acc[MFRAG][NFRAG][4];
#pragma unroll
    for (int i = 0; i < MFRAG; i++)
#pragma unroll
        for (int j = 0; j < NFRAG; j++)
#pragma unroll
            for (int r = 0; r < 4; r++) acc[i][j][r] = 0.f;

    for (int k0 = 0; k0 < K; k0 += BK) {
        // Stage A tile (transposed k-major in smem), tf32-rounded
#pragma unroll
        for (int idx = tid; idx < BM * BK; idx += NTHREADS) {
            int m = idx / BK;
            int k = idx - m * BK;
            int gk = k0 + k;
            float v = (gk < K) ? A[(size_t)(bm0 + m) * K + gk] : 0.f;
            As[k][m] = __uint_as_float(f2tf32(v));
        }
        // Stage B tile
#pragma unroll
        for (int idx = tid; idx < BN * BK; idx += NTHREADS) {
            int n = idx / BK;
            int k = idx - n * BK;
            int gn = bn0 + n;
            int gk = k0 + k;
            float v = (gn < N && gk < K) ? Bm[(size_t)gn * K + gk] : 0.f;
            Bs[k][n] = __uint_as_float(f2tf32(v));
        }
        __syncthreads();

#pragma unroll
        for (int kk = 0; kk < BK; kk += 8) {
            uint32_t afrag[MFRAG][4];
#pragma unroll
            for (int i = 0; i < MFRAG; i++) {
                int mrow = wm + i * 16 + gr;
                afrag[i][0] = __float_as_uint(As[kk + gc][mrow]);
                afrag[i][1] = __float_as_uint(As[kk + gc][mrow + 8]);
                afrag[i][2] = __float_as_uint(As[kk + gc + 4][mrow]);
                afrag[i][3] = __float_as_uint(As[kk + gc + 4][mrow + 8]);
            }
            uint32_t bfrag[NFRAG][2];
#pragma unroll
            for (int j = 0; j < NFRAG; j++) {
                int ncol = wn + j * 8 + gr;
                bfrag[j][0] = __float_as_uint(Bs[kk + gc][ncol]);
                bfrag[j][1] = __float_as_uint(Bs[kk + gc + 4][ncol]);
            }
#pragma unroll
            for (int i = 0; i < MFRAG; i++)
#pragma unroll
                for (int j = 0; j < NFRAG; j++) MMA_TF32(acc[i][j], afrag[i], bfrag[j]);
        }
        __syncthreads();
    }

    // Epilogue: add bias, guarded store
#pragma unroll
    for (int i = 0; i < MFRAG; i++) {
#pragma unroll
        for (int j = 0; j < NFRAG; j++) {
            int mrow = bm0 + wm + i * 16 + gr;
            int ncol = bn0 + wn + j * 8 + gc * 2;
#pragma unroll
            for (int half = 0; half < 2; half++) {  // rows gr and gr+8
                int m = mrow + half * 8;
                float v0 = acc[i][j][half * 2 + 0];
                float v1 = acc[i][j][half * 2 + 1];
                if (ncol < N)     C[(size_t)m * N + ncol]     = v0 + bias[ncol];
                if (ncol + 1 < N) C[(size_t)m * N + ncol + 1] = v1 + bias[ncol + 1];
            }
        }
    }
}

// ---------------------------------------------------------------------------
// GRU elementwise update for step s (PyTorch convention: reset applied to
// (W_hn h + b_hn), which is already inside hg).
// ---------------------------------------------------------------------------
__global__ void gru_update_kernel(const float* __restrict__ hg,
                                  const float* __restrict__ h_old,
                                  float* __restrict__ h_new, int s) {
    int idx = blockIdx.x * blockDim.x + threadIdx.x;
    if (idx >= B_ * H_) return;
    int b = idx / H_;
    int j = idx - b * H_;

    const float* xgr = g_xg + ((size_t)b * S_ + s) * G_;
    float xr = xgr[j];
    float xz = xgr[H_ + j];
    float xn = xgr[2 * H_ + j];
    float hr = hg[b * G_ + j];
    float hz = hg[b * G_ + H_ + j];
    float hn = hg[b * G_ + 2 * H_ + j];

    float r = 1.f / (1.f + expf(-(xr + hr)));
    float z = 1.f / (1.f + expf(-(xz + hz)));
    float n = tanhf(xn + r * hn);
    float h = (1.f - z) * n + z * h_old[idx];

    h_new[idx] = h;
    g_hs[((size_t)b * S_ + s) * H_ + j] = h;
}

// ---------------------------------------------------------------------------
// kernel_launch: graph-capturable sequence on the default stream
// ---------------------------------------------------------------------------
extern "C" void kernel_launch(void* const* d_in, const int* in_sizes, int n_in,
                              void* d_out, int out_size) {
    const int*   tgt  = (const int*)  d_in[0];
    const float* sv   = (const float*)d_in[1];
    const float* emb  = (const float*)d_in[2];
    const float* Wih  = (const float*)d_in[3];
    const float* Whh  = (const float*)d_in[4];
    const float* bih  = (const float*)d_in[5];
    const float* bhh  = (const float*)d_in[6];
    const float* Wout = (const float*)d_in[7];
    const float* bout = (const float*)d_in[8];
    float* out = (float*)d_out;

    float *p_emb, *p_xg, *p_hg, *p_hs, *p_h0, *p_h1;
    cudaGetSymbolAddress((void**)&p_emb, g_emb);
    cudaGetSymbolAddress((void**)&p_xg,  g_xg);
    cudaGetSymbolAddress((void**)&p_hg,  g_hg);
    cudaGetSymbolAddress((void**)&p_hs,  g_hs);
    cudaGetSymbolAddress((void**)&p_h0,  g_h0);
    cudaGetSymbolAddress((void**)&p_h1,  g_h1);

    // Phase 0: gather embeddings + init h0
    gather_init_kernel<<<(M_ * E_ + 255) / 256, 256>>>(tgt, emb, sv);

    // Phase A: x_gates = emb @ W_ih^T + b_ih    [2048 x 7200], K=300
    {
        dim3 grid(M_ / 128, (G_ + 127) / 128);
        gemm_tf32_kernel<128, 128, 16, 32, 64><<<grid, 256>>>(
            p_emb, Wih, bih, p_xg, M_, G_, E_);
    }

    // Phase B: 64 sequential GRU steps
    float* hcur = p_h0;
    float* hnext = p_h1;
    for (int s = 0; s < S_; s++) {
        dim3 grid(1, (G_ + 63) / 64);  // M=32 -> 1 m-tile, 113 n-tiles
        gemm_tf32_kernel<32, 64, 16, 32, 8><<<grid, 256>>>(
            hcur, Whh, bhh, p_hg, B_, G_, H_);
        gru_update_kernel<<<(B_ * H_ + 255) / 256, 256>>>(p_hg, hcur, hnext, s);
        float* t = hcur; hcur = hnext; hnext = t;
    }

    // Phase C: logits = hs @ W_out^T + b_out    [2048 x 20000], K=2400
    {
        dim3 grid(M_ / 128, (V_ + 127) / 128);
        gemm_tf32_kernel<128, 128, 16, 32, 64><<<grid, 256>>>(
            p_hs, Wout, bout, out, M_, V_, H_);
    }
}

// round 3
// speedup vs baseline: 2.6503x; 2.6503x over previous
#include <cuda_runtime.h>
#include <cstdint>

// Problem constants
constexpr int V_ = 20000;
constexpr int E_ = 300;
constexpr int H_ = 2400;
constexpr int B_ = 32;
constexpr int S_ = 64;
constexpr int M_ = B_ * S_;   // 2048
constexpr int G_ = 3 * H_;    // 7200

// Scratch (static device globals; no runtime allocation)
__device__ float g_emb[M_ * E_];                 // 2.4 MB   gathered+rounded embeddings
__device__ float g_xg[(size_t)M_ * G_];          // 59 MB    input gate preacts (interleaved)
__device__ float g_hs[M_ * H_];                  // 19.7 MB  hidden states (tf32-rounded)
__device__ float g_h0[B_ * H_];
__device__ float g_h1[B_ * H_];
__device__ float g_wih[(size_t)G_ * E_];         // 8.6 MB   reordered+rounded W_ih
__device__ float g_whh[(size_t)G_ * H_];         // 69 MB    reordered+rounded W_hh
__device__ float g_wout[(size_t)V_ * H_];        // 192 MB   rounded W_out
__device__ float g_bih[G_];
__device__ float g_bhh[G_];

// ---------------------------------------------------------------------------
__device__ __forceinline__ uint32_t f2tf32(float x) {
    uint32_t u;
    asm("cvt.rna.tf32.f32 %0, %1;" : "=r"(u) : "f"(x));
    return u;
}
__device__ __forceinline__ float rna(float x) { return __uint_as_float(f2tf32(x)); }

#define MMA_TF32(c, a, b)                                                     \
    asm volatile(                                                             \
        "mma.sync.aligned.m16n8k8.row.col.f32.tf32.tf32.f32 "                 \
        "{%0,%1,%2,%3}, {%4,%5,%6,%7}, {%8,%9}, {%0,%1,%2,%3};\n"             \
        : "+f"((c)[0]), "+f"((c)[1]), "+f"((c)[2]), "+f"((c)[3])              \
        : "r"((a)[0]), "r"((a)[1]), "r"((a)[2]), "r"((a)[3]),                 \
          "r"((b)[0]), "r"((b)[1]))

// ---------------------------------------------------------------------------
// Pre-pass: reorder gate weights to interleaved layout [3j+g] and tf32-round.
// ---------------------------------------------------------------------------
__global__ void prep_whh(const float* __restrict__ Whh) {
    size_t n = (size_t)G_ * H_;
    for (size_t i = (size_t)blockIdx.x * blockDim.x + threadIdx.x; i < n;
         i += (size_t)gridDim.x * blockDim.x) {
        int np = (int)(i / H_);
        int k = (int)(i - (size_t)np * H_);
        int j = np / 3, g = np % 3;
        g_whh[i] = rna(Whh[(size_t)(g * H_ + j) * H_ + k]);
    }
}
__global__ void prep_wih_bias(const float* __restrict__ Wih,
                              const float* __restrict__ bih,
                              const float* __restrict__ bhh) {
    size_t n = (size_t)G_ * E_;
    for (size_t i = (size_t)blockIdx.x * blockDim.x + threadIdx.x; i < n;
         i += (size_t)gridDim.x * blockDim.x) {
        int np = (int)(i / E_);
        int k = (int)(i - (size_t)np * E_);
        int j = np / 3, g = np % 3;
        g_wih[i] = rna(Wih[(size_t)(g * H_ + j) * E_ + k]);
    }
    int t = blockIdx.x * blockDim.x + threadIdx.x;
    if (t < G_) {
        int j = t / 3, g = t % 3;
        g_bih[t] = bih[g * H_ + j];
        g_bhh[t] = bhh[g * H_ + j];
    }
}
__global__ void prep_wout(const float* __restrict__ Wout) {
    size_t n = (size_t)V_ * H_;
    for (size_t i = (size_t)blockIdx.x * blockDim.x + threadIdx.x; i < n;
         i += (size_t)gridDim.x * blockDim.x)
        g_wout[i] = rna(Wout[i]);
}

// ---------------------------------------------------------------------------
// Embedding gather (rounded) + h0 init (rounded)
// ---------------------------------------------------------------------------
__global__ void gather_init_kernel(const int* __restrict__ tgt,
                                   const float* __restrict__ emb_table,
                                   const float* __restrict__ sentence_vec) {
    int idx = blockIdx.x * blockDim.x + threadIdx.x;
    if (idx < M_ * E_) {
        int m = idx / E_;
        int e = idx - m * E_;
        g_emb[idx] = rna(emb_table[(size_t)tgt[m] * E_ + e]);
    }
    if (idx < B_ * H_) g_h0[idx] = rna(sentence_vec[idx]);
}

// ---------------------------------------------------------------------------
// Pipelined tf32 GEMM: C[m,n] = sum_k A[m,k]*B[n,k] (+bias / GRU epilogue)
// A: [M,K] row-major (pre-rounded), B: [N,K] row-major (pre-rounded).
// 3-stage cp.async pipeline, BK=32. One commit_group per main-loop iteration
// (empty commit in the tail) so cp.async.wait_group 1 always forces the tile
// about to be consumed to completion.
// EPI 0: C = acc + bias.  EPI 1: fused GRU update (BM=32, BN=96).
// ---------------------------------------------------------------------------
template <int BM, int BN, int BK, int WM, int WN, int EPI>
__global__ void __launch_bounds__(256)
gemm_pipe(const float* __restrict__ A, const float* __restrict__ Bmat,
          const float* __restrict__ bias, float* __restrict__ C,
          int M, int N, int K,
          const float* __restrict__ xg, const float* __restrict__ h_old,
          float* __restrict__ h_new, float* __restrict__ hs, int s) {
    constexpr int WARPS_M = BM / WM;
    constexpr int WARPS_N = BN / WN;
    constexpr int NT = WARPS_M * WARPS_N * 32;
    static_assert(NT == 256, "need 256 threads");
    constexpr int MFRAG = WM / 16;
    constexpr int NFRAG = WN / 8;
    constexpr int LDA = BK + 4;      // float stride, keeps 16B alignment, kills conflicts
    constexpr int STAGES = 3;
    constexpr int A_ST = BM * LDA;
    constexpr int B_ST = BN * LDA;
    constexpr int ST = A_ST + B_ST;

    extern __shared__ float smbuf[];

    const int tid = threadIdx.x;
    const int warp = tid >> 5, lane = tid & 31;
    const int gr = lane >> 2, gc = lane & 3;
    const int wm = (warp % WARPS_M) * WM;
    const int wn = (warp / WARPS_M) * WN;
    const int bm0 = blockIdx.x * BM;
    const int bn0 = blockIdx.y * BN;

    const int T = (K + BK - 1) / BK;

    auto load_tile = [&](int stage, int t) {
        float* sA = smbuf + stage * ST;
        float* sB = sA + A_ST;
        const int k0 = t * BK;
        constexpr int CHA = BM * (BK / 4);
#pragma unroll
        for (int c = tid; c < CHA; c += NT) {
            int row = c / (BK / 4), ch = c % (BK / 4);
            int gk = k0 + ch * 4;
            const float* src = A + (size_t)(bm0 + row) * K + gk;
            uint32_t dst = (uint32_t)__cvta_generic_to_shared(sA + row * LDA + ch * 4);
            int bytes = (gk < K) ? 16 : 0;
            asm volatile("cp.async.cg.shared.global [%0], [%1], 16, %2;\n" ::
                         "r"(dst), "l"(src), "r"(bytes));
        }
        constexpr int CHB = BN * (BK / 4);
#pragma unroll
        for (int c = tid; c < CHB; c += NT) {
            int row = c / (BK / 4), ch = c % (BK / 4);
            int gk = k0 + ch * 4, gn = bn0 + row;
            const float* src = Bmat + (size_t)gn * K + gk;
            uint32_t dst = (uint32_t)__cvta_generic_to_shared(sB + row * LDA + ch * 4);
            int bytes = (gk < K && gn < N) ? 16 : 0;
            asm volatile("cp.async.cg.shared.global [%0], [%1], 16, %2;\n" ::
                         "r"(dst), "l"(src), "r"(bytes));
        }
        asm volatile("cp.async.commit_group;\n");
    };

    float acc[MFRAG][NFRAG][4];
#pragma unroll
    for (int i = 0; i < MFRAG; i++)
#pragma unroll
        for (int j = 0; j < NFRAG; j++)
#pragma unroll
            for (int r = 0; r < 4; r++) acc[i][j][r] = 0.f;

    const int npre = (STAGES - 1 < T) ? STAGES - 1 : T;
    for (int t = 0; t < npre; t++) load_tile(t, t);

    for (int t = 0; t < T; t++) {
        asm volatile("cp.async.wait_group %0;\n" ::"n"(STAGES - 2));
        __syncthreads();
        if (t + STAGES - 1 < T) {
            load_tile((t + STAGES - 1) % STAGES, t + STAGES - 1);
        } else {
            // Tail: keep one commit per iteration so wait_group 1 above always
            // retires the group for the tile this iteration consumes.
            asm volatile("cp.async.commit_group;\n");
        }
        const float* sA = smbuf + (t % STAGES) * ST;
        const float* sB = sA + A_ST;
#pragma unroll
        for (int kk = 0; kk < BK; kk += 8) {
            uint32_t af[MFRAG][4];
#pragma unroll
            for (int i = 0; i < MFRAG; i++) {
                int m0 = wm + i * 16 + gr;
                af[i][0] = __float_as_uint(sA[m0 * LDA + kk + gc]);
                af[i][1] = __float_as_uint(sA[(m0 + 8) * LDA + kk + gc]);
                af[i][2] = __float_as_uint(sA[m0 * LDA + kk + gc + 4]);
                af[i][3] = __float_as_uint(sA[(m0 + 8) * LDA + kk + gc + 4]);
            }
            uint32_t bf[NFRAG][2];
#pragma unroll
            for (int j = 0; j < NFRAG; j++) {
                int n0 = wn + j * 8 + gr;
                bf[j][0] = __float_as_uint(sB[n0 * LDA + kk + gc]);
                bf[j][1] = __float_as_uint(sB[n0 * LDA + kk + gc + 4]);
            }
#pragma unroll
            for (int i = 0; i < MFRAG; i++)
#pragma unroll
                for (int j = 0; j < NFRAG; j++) MMA_TF32(acc[i][j], af[i], bf[j]);
        }
    }

    if (EPI == 0) {
        // Bias + store
#pragma unroll
        for (int i = 0; i < MFRAG; i++)
#pragma unroll
            for (int j = 0; j < NFRAG; j++) {
                int n = bn0 + wn + j * 8 + gc * 2;
#pragma unroll
                for (int half = 0; half < 2; half++) {
                    int m = bm0 + wm + i * 16 + gr + half * 8;
                    float v0 = acc[i][j][half * 2 + 0];
                    float v1 = acc[i][j][half * 2 + 1];
                    if (n < N)     C[(size_t)m * N + n]     = v0 + bias[n];
                    if (n + 1 < N) C[(size_t)m * N + n + 1] = v1 + bias[n + 1];
                }
            }
    } else {
        // Fused GRU update. BM=32 (batch), BN=96 = 32 hidden units x 3 gates
        // (interleaved layout r,z,n). acc -> smem -> per-(b,j) update.
        __syncthreads();
        float* hg = smbuf;  // 32*96 floats, aliases stage memory (safe after sync)
#pragma unroll
        for (int j = 0; j < NFRAG; j++) {
            int m0 = wm + gr;
            int n0 = wn + j * 8 + gc * 2;
            hg[m0 * BN + n0]           = acc[0][j][0];
            hg[m0 * BN + n0 + 1]       = acc[0][j][1];
            hg[(m0 + 8) * BN + n0]     = acc[0][j][2];
            hg[(m0 + 8) * BN + n0 + 1] = acc[0][j][3];
        }
        __syncthreads();
        const int jbase = bn0 / 3;
        for (int it = tid; it < B_ * (BN / 3); it += NT) {
            int b = it / (BN / 3);
            int lj = it % (BN / 3);
            int jg = jbase + lj;
            float hr = hg[b * BN + 3 * lj + 0] + bias[bn0 + 3 * lj + 0];
            float hz = hg[b * BN + 3 * lj + 1] + bias[bn0 + 3 * lj + 1];
            float hn = hg[b * BN + 3 * lj + 2] + bias[bn0 + 3 * lj + 2];
            const float* xrow = xg + (size_t)(b * S_ + s) * G_ + bn0 + 3 * lj;
            float xr = xrow[0], xz = xrow[1], xn = xrow[2];
            float r = 1.f / (1.f + expf(-(xr + hr)));
            float z = 1.f / (1.f + expf(-(xz + hz)));
            float nn = tanhf(xn + r * hn);
            float h = (1.f - z) * nn + z * h_old[b * H_ + jg];
            float hrnd = rna(h);
            h_new[b * H_ + jg] = hrnd;
            hs[(size_t)(b * S_ + s) * H_ + jg] = hrnd;
        }
    }
}

// ---------------------------------------------------------------------------
constexpr int SMEM_BIG = 3 * (128 + 128) * (32 + 4) * 4;  // 110592 B
constexpr int SMEM_REC = 3 * (32 + 96) * (32 + 4) * 4;    //  55296 B

extern "C" void kernel_launch(void* const* d_in, const int* in_sizes, int n_in,
                              void* d_out, int out_size) {
    const int*   tgt  = (const int*)  d_in[0];
    const float* sv   = (const float*)d_in[1];
    const float* emb  = (const float*)d_in[2];
    const float* Wih  = (const float*)d_in[3];
    const float* Whh  = (const float*)d_in[4];
    const float* bih  = (const float*)d_in[5];
    const float* bhh  = (const float*)d_in[6];
    const float* Wout = (const float*)d_in[7];
    const float* bout = (const float*)d_in[8];
    float* out = (float*)d_out;

    cudaFuncSetAttribute(gemm_pipe<128, 128, 32, 32, 64, 0>,
                         cudaFuncAttributeMaxDynamicSharedMemorySize, SMEM_BIG);
    cudaFuncSetAttribute(gemm_pipe<32, 96, 32, 16, 24, 1>,
                         cudaFuncAttributeMaxDynamicSharedMemorySize, SMEM_REC);

    float *p_emb, *p_xg, *p_hs, *p_h0, *p_h1, *p_wih, *p_whh, *p_wout, *p_bih, *p_bhh;
    cudaGetSymbolAddress((void**)&p_emb, g_emb);
    cudaGetSymbolAddress((void**)&p_xg,  g_xg);
    cudaGetSymbolAddress((void**)&p_hs,  g_hs);
    cudaGetSymbolAddress((void**)&p_h0,  g_h0);
    cudaGetSymbolAddress((void**)&p_h1,  g_h1);
    cudaGetSymbolAddress((void**)&p_wih, g_wih);
    cudaGetSymbolAddress((void**)&p_whh, g_whh);
    cudaGetSymbolAddress((void**)&p_wout, g_wout);
    cudaGetSymbolAddress((void**)&p_bih, g_bih);
    cudaGetSymbolAddress((void**)&p_bhh, g_bhh);

    // Pre-pass: weight reorder / tf32 rounding
    prep_whh<<<2048, 256>>>(Whh);
    prep_wih_bias<<<2048, 256>>>(Wih, bih, bhh);
    prep_wout<<<4096, 256>>>(Wout);

    // Gather + h0
    gather_init_kernel<<<(M_ * E_ + 255) / 256, 256>>>(tgt, emb, sv);

    // Phase A: x_gates (interleaved) = emb @ W_ih'^T + b_ih'
    {
        dim3 grid(M_ / 128, (G_ + 127) / 128);
        gemm_pipe<128, 128, 32, 32, 64, 0><<<grid, 256, SMEM_BIG>>>(
            p_emb, p_wih, p_bih, p_xg, M_, G_, E_,
            nullptr, nullptr, nullptr, nullptr, 0);
    }

    // Phase B: 64 fused GEMM+GRU steps
    float* hcur = p_h0;
    float* hnext = p_h1;
    for (int s = 0; s < S_; s++) {
        dim3 grid(1, G_ / 96);  // 75 blocks
        gemm_pipe<32, 96, 32, 16, 24, 1><<<grid, 256, SMEM_REC>>>(
            hcur, p_whh, p_bhh, nullptr, B_, G_, H_,
            p_xg, hcur, hnext, p_hs, s);
        float* t = hcur; hcur = hnext; hnext = t;
    }

    // Phase C: logits = hs @ W_out^T + b_out
    {
        dim3 grid(M_ / 128, (V_ + 127) / 128);
        gemm_pipe<128, 128, 32, 32, 64, 0><<<grid, 256, SMEM_BIG>>>(
            p_hs, p_wout, bout, out, M_, V_, H_,
            nullptr, nullptr, nullptr, nullptr, 0);
    }
}

// round 4
// speedup vs baseline: 3.0026x; 1.1329x over previous
#include <cuda_runtime.h>
#include <cstdint>

// Problem constants
constexpr int V_ = 20000;
constexpr int E_ = 300;
constexpr int H_ = 2400;
constexpr int B_ = 32;
constexpr int S_ = 64;
constexpr int M_ = B_ * S_;   // 2048
constexpr int G_ = 3 * H_;    // 7200

// Scratch (static device globals; no runtime allocation)
__device__ float g_emb[M_ * E_];
__device__ float g_xg[(size_t)M_ * G_];
__device__ float g_hs[M_ * H_];
__device__ float g_h0[B_ * H_];
__device__ float g_h1[B_ * H_];
__device__ float g_wih[(size_t)G_ * E_];
__device__ float g_whh[(size_t)G_ * H_];
__device__ float g_wout[(size_t)V_ * H_];
__device__ float g_bih[G_];
__device__ float g_bhh[G_];

// ---------------------------------------------------------------------------
__device__ __forceinline__ uint32_t f2tf32(float x) {
    uint32_t u;
    asm("cvt.rna.tf32.f32 %0, %1;" : "=r"(u) : "f"(x));
    return u;
}
__device__ __forceinline__ float rna(float x) { return __uint_as_float(f2tf32(x)); }

#define MMA_TF32(c, a, b)                                                     \
    asm volatile(                                                             \
        "mma.sync.aligned.m16n8k8.row.col.f32.tf32.tf32.f32 "                 \
        "{%0,%1,%2,%3}, {%4,%5,%6,%7}, {%8,%9}, {%0,%1,%2,%3};\n"             \
        : "+f"((c)[0]), "+f"((c)[1]), "+f"((c)[2]), "+f"((c)[3])              \
        : "r"((a)[0]), "r"((a)[1]), "r"((a)[2]), "r"((a)[3]),                 \
          "r"((b)[0]), "r"((b)[1]))

// ---------------------------------------------------------------------------
// Pre-pass: reorder gate weights to interleaved layout [3j+g] and tf32-round.
// ---------------------------------------------------------------------------
__global__ void prep_whh(const float* __restrict__ Whh) {
    size_t n = (size_t)G_ * H_;
    for (size_t i = (size_t)blockIdx.x * blockDim.x + threadIdx.x; i < n;
         i += (size_t)gridDim.x * blockDim.x) {
        int np = (int)(i / H_);
        int k = (int)(i - (size_t)np * H_);
        int j = np / 3, g = np % 3;
        g_whh[i] = rna(Whh[(size_t)(g * H_ + j) * H_ + k]);
    }
}
__global__ void prep_wih_bias(const float* __restrict__ Wih,
                              const float* __restrict__ bih,
                              const float* __restrict__ bhh) {
    size_t n = (size_t)G_ * E_;
    for (size_t i = (size_t)blockIdx.x * blockDim.x + threadIdx.x; i < n;
         i += (size_t)gridDim.x * blockDim.x) {
        int np = (int)(i / E_);
        int k = (int)(i - (size_t)np * E_);
        int j = np / 3, g = np % 3;
        g_wih[i] = rna(Wih[(size_t)(g * H_ + j) * E_ + k]);
    }
    int t = blockIdx.x * blockDim.x + threadIdx.x;
    if (t < G_) {
        int j = t / 3, g = t % 3;
        g_bih[t] = bih[g * H_ + j];
        g_bhh[t] = bhh[g * H_ + j];
    }
}
__global__ void prep_wout(const float* __restrict__ Wout) {
    size_t n = (size_t)V_ * H_;
    for (size_t i = (size_t)blockIdx.x * blockDim.x + threadIdx.x; i < n;
         i += (size_t)gridDim.x * blockDim.x)
        g_wout[i] = rna(Wout[i]);
}

// ---------------------------------------------------------------------------
__global__ void gather_init_kernel(const int* __restrict__ tgt,
                                   const float* __restrict__ emb_table,
                                   const float* __restrict__ sentence_vec) {
    int idx = blockIdx.x * blockDim.x + threadIdx.x;
    if (idx < M_ * E_) {
        int m = idx / E_;
        int e = idx - m * E_;
        g_emb[idx] = rna(emb_table[(size_t)tgt[m] * E_ + e]);
    }
    if (idx < B_ * H_) g_h0[idx] = rna(sentence_vec[idx]);
}

// ---------------------------------------------------------------------------
// Pipelined tf32 GEMM: C[m,n] = sum_k A[m,k]*B[n,k] (+bias / GRU epilogue)
// 3-stage cp.async pipeline, BK=32, one commit per iteration (empty in tail).
// EPI 0: C = acc + bias.  EPI 1: fused GRU update (BM=32).
// ---------------------------------------------------------------------------
template <int BM, int BN, int BK, int WM, int WN, int EPI>
__global__ void __launch_bounds__((BM / WM) * (BN / WN) * 32)
gemm_pipe(const float* __restrict__ A, const float* __restrict__ Bmat,
          const float* __restrict__ bias, float* __restrict__ C,
          int M, int N, int K,
          const float* __restrict__ xg, const float* __restrict__ h_old,
          float* __restrict__ h_new, float* __restrict__ hs, int s) {
    constexpr int WARPS_M = BM / WM;
    constexpr int WARPS_N = BN / WN;
    constexpr int NT = WARPS_M * WARPS_N * 32;
    constexpr int MFRAG = WM / 16;
    constexpr int NFRAG = WN / 8;
    constexpr int LDA = BK + 4;
    constexpr int STAGES = 3;
    constexpr int A_ST = BM * LDA;
    constexpr int B_ST = BN * LDA;
    constexpr int ST = A_ST + B_ST;

    extern __shared__ float smbuf[];

    const int tid = threadIdx.x;
    const int warp = tid >> 5, lane = tid & 31;
    const int gr = lane >> 2, gc = lane & 3;
    const int wm = (warp % WARPS_M) * WM;
    const int wn = (warp / WARPS_M) * WN;
    const int bm0 = blockIdx.x * BM;
    const int bn0 = blockIdx.y * BN;

    const int T = (K + BK - 1) / BK;

    auto load_tile = [&](int stage, int t) {
        float* sA = smbuf + stage * ST;
        float* sB = sA + A_ST;
        const int k0 = t * BK;
        constexpr int CHA = BM * (BK / 4);
#pragma unroll
        for (int c = tid; c < CHA; c += NT) {
            int row = c / (BK / 4), ch = c % (BK / 4);
            int gk = k0 + ch * 4;
            const float* src = A + (size_t)(bm0 + row) * K + gk;
            uint32_t dst = (uint32_t)__cvta_generic_to_shared(sA + row * LDA + ch * 4);
            int bytes = (gk < K) ? 16 : 0;
            asm volatile("cp.async.cg.shared.global [%0], [%1], 16, %2;\n" ::
                         "r"(dst), "l"(src), "r"(bytes));
        }
        constexpr int CHB = BN * (BK / 4);
#pragma unroll
        for (int c = tid; c < CHB; c += NT) {
            int row = c / (BK / 4), ch = c % (BK / 4);
            int gk = k0 + ch * 4, gn = bn0 + row;
            const float* src = Bmat + (size_t)gn * K + gk;
            uint32_t dst = (uint32_t)__cvta_generic_to_shared(sB + row * LDA + ch * 4);
            int bytes = (gk < K && gn < N) ? 16 : 0;
            asm volatile("cp.async.cg.shared.global [%0], [%1], 16, %2;\n" ::
                         "r"(dst), "l"(src), "r"(bytes));
        }
        asm volatile("cp.async.commit_group;\n");
    };

    float acc[MFRAG][NFRAG][4];
#pragma unroll
    for (int i = 0; i < MFRAG; i++)
#pragma unroll
        for (int j = 0; j < NFRAG; j++)
#pragma unroll
            for (int r = 0; r < 4; r++) acc[i][j][r] = 0.f;

    const int npre = (STAGES - 1 < T) ? STAGES - 1 : T;
    for (int t = 0; t < npre; t++) load_tile(t, t);

    for (int t = 0; t < T; t++) {
        asm volatile("cp.async.wait_group %0;\n" ::"n"(STAGES - 2));
        __syncthreads();
        if (t + STAGES - 1 < T) {
            load_tile((t + STAGES - 1) % STAGES, t + STAGES - 1);
        } else {
            asm volatile("cp.async.commit_group;\n");
        }
        const float* sA = smbuf + (t % STAGES) * ST;
        const float* sB = sA + A_ST;
#pragma unroll
        for (int kk = 0; kk < BK; kk += 8) {
            uint32_t af[MFRAG][4];
#pragma unroll
            for (int i = 0; i < MFRAG; i++) {
                int m0 = wm + i * 16 + gr;
                af[i][0] = __float_as_uint(sA[m0 * LDA + kk + gc]);
                af[i][1] = __float_as_uint(sA[(m0 + 8) * LDA + kk + gc]);
                af[i][2] = __float_as_uint(sA[m0 * LDA + kk + gc + 4]);
                af[i][3] = __float_as_uint(sA[(m0 + 8) * LDA + kk + gc + 4]);
            }
            uint32_t bf[NFRAG][2];
#pragma unroll
            for (int j = 0; j < NFRAG; j++) {
                int n0 = wn + j * 8 + gr;
                bf[j][0] = __float_as_uint(sB[n0 * LDA + kk + gc]);
                bf[j][1] = __float_as_uint(sB[n0 * LDA + kk + gc + 4]);
            }
#pragma unroll
            for (int i = 0; i < MFRAG; i++)
#pragma unroll
                for (int j = 0; j < NFRAG; j++) MMA_TF32(acc[i][j], af[i], bf[j]);
        }
    }

    if (EPI == 0) {
#pragma unroll
        for (int i = 0; i < MFRAG; i++)
#pragma unroll
            for (int j = 0; j < NFRAG; j++) {
                int n = bn0 + wn + j * 8 + gc * 2;
#pragma unroll
                for (int half = 0; half < 2; half++) {
                    int m = bm0 + wm + i * 16 + gr + half * 8;
                    float v0 = acc[i][j][half * 2 + 0];
                    float v1 = acc[i][j][half * 2 + 1];
                    if (n < N)     C[(size_t)m * N + n]     = v0 + bias[n];
                    if (n + 1 < N) C[(size_t)m * N + n + 1] = v1 + bias[n + 1];
                }
            }
    } else {
        // Fused GRU update. BM=32 (batch), BN = 3*(BN/3) hidden units x gates
        // interleaved (r,z,n). acc -> smem -> per-(b,j) update.
        __syncthreads();
        float* hg = smbuf;  // BM*BN floats, aliases stage memory (safe after sync)
#pragma unroll
        for (int j = 0; j < NFRAG; j++) {
            int m0 = wm + gr;
            int n0 = wn + j * 8 + gc * 2;
            hg[m0 * BN + n0]           = acc[0][j][0];
            hg[m0 * BN + n0 + 1]       = acc[0][j][1];
            hg[(m0 + 8) * BN + n0]     = acc[0][j][2];
            hg[(m0 + 8) * BN + n0 + 1] = acc[0][j][3];
        }
        __syncthreads();
        const int jbase = bn0 / 3;
        for (int it = tid; it < B_ * (BN / 3); it += NT) {
            int b = it / (BN / 3);
            int lj = it % (BN / 3);
            int jg = jbase + lj;
            float hr = hg[b * BN + 3 * lj + 0] + bias[bn0 + 3 * lj + 0];
            float hz = hg[b * BN + 3 * lj + 1] + bias[bn0 + 3 * lj + 1];
            float hn = hg[b * BN + 3 * lj + 2] + bias[bn0 + 3 * lj + 2];
            const float* xrow = xg + (size_t)(b * S_ + s) * G_ + bn0 + 3 * lj;
            float xr = xrow[0], xz = xrow[1], xn = xrow[2];
            float r = 1.f / (1.f + expf(-(xr + hr)));
            float z = 1.f / (1.f + expf(-(xz + hz)));
            float nn = tanhf(xn + r * hn);
            float h = (1.f - z) * nn + z * h_old[b * H_ + jg];
            float hrnd = rna(h);
            h_new[b * H_ + jg] = hrnd;
            hs[(size_t)(b * S_ + s) * H_ + jg] = hrnd;
        }
    }
}

// ---------------------------------------------------------------------------
constexpr int SMEM_BIG = 3 * (128 + 256) * (32 + 4) * 4;  // 165888 B (phase C)
constexpr int SMEM_A_  = 3 * (128 + 128) * (32 + 4) * 4;  // 110592 B (phase A)
constexpr int SMEM_REC = 3 * (32 + 48) * (32 + 4) * 4;    //  34560 B (recurrence)

extern "C" void kernel_launch(void* const* d_in, const int* in_sizes, int n_in,
                              void* d_out, int out_size) {
    const int*   tgt  = (const int*)  d_in[0];
    const float* sv   = (const float*)d_in[1];
    const float* emb  = (const float*)d_in[2];
    const float* Wih  = (const float*)d_in[3];
    const float* Whh  = (const float*)d_in[4];
    const float* bih  = (const float*)d_in[5];
    const float* bhh  = (const float*)d_in[6];
    const float* Wout = (const float*)d_in[7];
    const float* bout = (const float*)d_in[8];
    float* out = (float*)d_out;

    cudaFuncSetAttribute(gemm_pipe<128, 256, 32, 32, 128, 0>,
                         cudaFuncAttributeMaxDynamicSharedMemorySize, SMEM_BIG);
    cudaFuncSetAttribute(gemm_pipe<128, 128, 32, 32, 64, 0>,
                         cudaFuncAttributeMaxDynamicSharedMemorySize, SMEM_A_);
    cudaFuncSetAttribute(gemm_pipe<32, 48, 32, 16, 24, 1>,
                         cudaFuncAttributeMaxDynamicSharedMemorySize, SMEM_REC);

    float *p_emb, *p_xg, *p_hs, *p_h0, *p_h1, *p_wih, *p_whh, *p_wout, *p_bih, *p_bhh;
    cudaGetSymbolAddress((void**)&p_emb, g_emb);
    cudaGetSymbolAddress((void**)&p_xg,  g_xg);
    cudaGetSymbolAddress((void**)&p_hs,  g_hs);
    cudaGetSymbolAddress((void**)&p_h0,  g_h0);
    cudaGetSymbolAddress((void**)&p_h1,  g_h1);
    cudaGetSymbolAddress((void**)&p_wih, g_wih);
    cudaGetSymbolAddress((void**)&p_whh, g_whh);
    cudaGetSymbolAddress((void**)&p_wout, g_wout);
    cudaGetSymbolAddress((void**)&p_bih, g_bih);
    cudaGetSymbolAddress((void**)&p_bhh, g_bhh);

    // Pre-pass: weight reorder / tf32 rounding
    prep_whh<<<2048, 256>>>(Whh);
    prep_wih_bias<<<2048, 256>>>(Wih, bih, bhh);
    prep_wout<<<4096, 256>>>(Wout);

    // Gather + h0
    gather_init_kernel<<<(M_ * E_ + 255) / 256, 256>>>(tgt, emb, sv);

    // Phase A: x_gates (interleaved) = emb @ W_ih'^T + b_ih'
    {
        dim3 grid(M_ / 128, (G_ + 127) / 128);
        gemm_pipe<128, 128, 32, 32, 64, 0><<<grid, 256, SMEM_A_>>>(
            p_emb, p_wih, p_bih, p_xg, M_, G_, E_,
            nullptr, nullptr, nullptr, nullptr, 0);
    }

    // Phase B: 64 fused GEMM+GRU steps, 150 CTAs (full chip), BN=48
    float* hcur = p_h0;
    float* hnext = p_h1;
    for (int s = 0; s < S_; s++) {
        dim3 grid(1, G_ / 48);  // 150 blocks
        gemm_pipe<32, 48, 32, 16, 24, 1><<<grid, 128, SMEM_REC>>>(
            hcur, p_whh, p_bhh, nullptr, B_, G_, H_,
            p_xg, hcur, hnext, p_hs, s);
        float* t = hcur; hcur = hnext; hnext = t;
    }

    // Phase C: logits = hs @ W_out^T + b_out, 128x256 tiles
    {
        dim3 grid(M_ / 128, (V_ + 255) / 256);
        gemm_pipe<128, 256, 32, 32, 128, 0><<<grid, 256, SMEM_BIG>>>(
            p_hs, p_wout, bout, out, M_, V_, H_,
            nullptr, nullptr, nullptr, nullptr, 0);
    }
}

// round 6
// speedup vs baseline: 4.5659x; 1.5206x over previous
#include <cuda_runtime.h>
#include <cuda_fp16.h>
#include <cstdint>

// Problem constants
constexpr int V_ = 20000;
constexpr int E_ = 300;
constexpr int EK_ = 320;      // E padded to BK multiple (zero-filled)
constexpr int H_ = 2400;
constexpr int B_ = 32;
constexpr int S_ = 64;
constexpr int M_ = B_ * S_;   // 2048
constexpr int G_ = 3 * H_;    // 7200

// Scratch (static device globals; no runtime allocation)
__device__ __half g_emb[(size_t)M_ * EK_];        // 1.3 MB  gathered fp16, padded
__device__ float  g_xg[(size_t)M_ * G_];          // 59 MB   input gate preacts fp32
__device__ __half g_hs[(size_t)M_ * H_];          // 9.8 MB  hidden states fp16
__device__ __half g_h0[B_ * H_];
__device__ __half g_h1[B_ * H_];
__device__ __half g_wih[(size_t)G_ * EK_];        // 4.6 MB  reordered fp16, padded
__device__ __half g_whh[(size_t)G_ * H_];         // 34.6 MB reordered fp16
__device__ __half g_wout[(size_t)V_ * H_];        // 96 MB   fp16
__device__ float  g_bih[G_];
__device__ float  g_bhh[G_];

// ---------------------------------------------------------------------------
#define MMA_F16(c, a, b)                                                      \
    asm volatile(                                                             \
        "mma.sync.aligned.m16n8k16.row.col.f32.f16.f16.f32 "                  \
        "{%0,%1,%2,%3}, {%4,%5,%6,%7}, {%8,%9}, {%0,%1,%2,%3};\n"             \
        : "+f"((c)[0]), "+f"((c)[1]), "+f"((c)[2]), "+f"((c)[3])              \
        : "r"((a)[0]), "r"((a)[1]), "r"((a)[2]), "r"((a)[3]),                 \
          "r"((b)[0]), "r"((b)[1]))

__device__ __forceinline__ void ldsm_x4(uint32_t& r0, uint32_t& r1,
                                        uint32_t& r2, uint32_t& r3, uint32_t a) {
    asm volatile("ldmatrix.sync.aligned.m8n8.x4.shared.b16 {%0,%1,%2,%3}, [%4];"
                 : "=r"(r0), "=r"(r1), "=r"(r2), "=r"(r3) : "r"(a));
}
__device__ __forceinline__ void ldsm_x2(uint32_t& r0, uint32_t& r1, uint32_t a) {
    asm volatile("ldmatrix.sync.aligned.m8n8.x2.shared.b16 {%0,%1}, [%2];"
                 : "=r"(r0), "=r"(r1) : "r"(a));
}

// ---------------------------------------------------------------------------
// Pre-pass: reorder gate weights to interleaved layout [3j+g], fp16 convert.
// ---------------------------------------------------------------------------
__global__ void prep_whh(const float* __restrict__ Whh) {
    size_t n = (size_t)G_ * H_;
    for (size_t i = (size_t)blockIdx.x * blockDim.x + threadIdx.x; i < n;
         i += (size_t)gridDim.x * blockDim.x) {
        int np = (int)(i / H_);
        int k = (int)(i - (size_t)np * H_);
        int j = np / 3, g = np % 3;
        g_whh[i] = __float2half_rn(Whh[(size_t)(g * H_ + j) * H_ + k]);
    }
}
__global__ void prep_wih_bias(const float* __restrict__ Wih,
                              const float* __restrict__ bih,
                              const float* __restrict__ bhh) {
    size_t n = (size_t)G_ * EK_;
    for (size_t i = (size_t)blockIdx.x * blockDim.x + threadIdx.x; i < n;
         i += (size_t)gridDim.x * blockDim.x) {
        int np = (int)(i / EK_);
        int k = (int)(i - (size_t)np * EK_);
        int j = np / 3, g = np % 3;
        g_wih[i] = (k < E_) ? __float2half_rn(Wih[(size_t)(g * H_ + j) * E_ + k])
                            : __half(0.f);
    }
    int t = blockIdx.x * blockDim.x + threadIdx.x;
    if (t < G_) {
        int j = t / 3, g = t % 3;
        g_bih[t] = bih[g * H_ + j];
        g_bhh[t] = bhh[g * H_ + j];
    }
}
__global__ void prep_wout(const float* __restrict__ Wout) {
    size_t n = (size_t)V_ * H_;
    for (size_t i = (size_t)blockIdx.x * blockDim.x + threadIdx.x; i < n;
         i += (size_t)gridDim.x * blockDim.x)
        g_wout[i] = __float2half_rn(Wout[i]);
}

__global__ void gather_init_kernel(const int* __restrict__ tgt,
                                   const float* __restrict__ emb_table,
                                   const float* __restrict__ sentence_vec) {
    int idx = blockIdx.x * blockDim.x + threadIdx.x;
    if (idx < M_ * EK_) {
        int m = idx / EK_;
        int e = idx - m * EK_;
        g_emb[idx] = (e < E_) ? __float2half_rn(emb_table[(size_t)tgt[m] * E_ + e])
                              : __half(0.f);
    }
    if (idx < B_ * H_) g_h0[idx] = __float2half_rn(sentence_vec[idx]);
}

// ---------------------------------------------------------------------------
// fp16 pipelined GEMM (HMMA m16n8k16 + ldmatrix):
//   C[m,n] = sum_k A[m,k]*B[n,k]  (+bias / fused GRU epilogue)
// A: [M,K] fp16 row-major,  B: [N,K] fp16 row-major.  K % BK == 0.
// STAGES-deep cp.async pipeline, one commit per iteration (empty in tail).
// EPI 0: C = acc + bias (fp32 out).  EPI 1: fused GRU update (BM=32).
// ---------------------------------------------------------------------------
template <int BM, int BN, int BK, int WM, int WN, int EPI, int STAGES>
__global__ void __launch_bounds__((BM / WM) * (BN / WN) * 32)
gemm_f16(const __half* __restrict__ A, const __half* __restrict__ Bmat,
         const float* __restrict__ bias, float* __restrict__ C,
         int M, int N, int K,
         const float* __restrict__ xg, const __half* __restrict__ h_old,
         __half* __restrict__ h_new, __half* __restrict__ hs, int s) {
    constexpr int WARPS_M = BM / WM;
    constexpr int WARPS_N = BN / WN;
    constexpr int NT = WARPS_M * WARPS_N * 32;
    constexpr int MFRAG = WM / 16;
    constexpr int NFRAG = WN / 8;
    constexpr int LDH = BK + 8;            // halfs; 80B row stride: 16B-aligned, conflict-free
    constexpr int A_ST = BM * LDH;
    constexpr int B_ST = BN * LDH;
    constexpr int ST = A_ST + B_ST;        // halfs per stage

    extern __shared__ __half smbuf[];

    const int tid = threadIdx.x;
    const int warp = tid >> 5, lane = tid & 31;
    const int gr = lane >> 2, gc = lane & 3;
    const int wm = (warp % WARPS_M) * WM;
    const int wn = (warp / WARPS_M) * WN;
    const int bm0 = blockIdx.x * BM;
    const int bn0 = blockIdx.y * BN;

    const uint32_t sbase = (uint32_t)__cvta_generic_to_shared(smbuf);

    // ldmatrix lane-address components
    const int sub = lane >> 3, lr = lane & 7;
    const int a_off = ((sub & 1) * 8 + lr) * LDH + (sub >> 1) * 8;  // halfs
    const int b_off = ((sub >> 1) * 8 + lr) * LDH + (sub & 1) * 8;  // halfs
    const int b2_off = ((lane & 15) >> 3) * 8 + (lr)*LDH;           // x2 leftover

    const int T = K / BK;

    auto load_tile = [&](int stage, int t) {
        const uint32_t sA = sbase + stage * ST * 2;
        const uint32_t sB = sA + A_ST * 2;
        const int k0 = t * BK;
        constexpr int CHR = BK / 8;                 // 16B chunks per row
        constexpr int CHA = BM * CHR;
#pragma unroll
        for (int c = tid; c < CHA; c += NT) {
            int row = c / CHR, ch = c % CHR;
            uint32_t dst = sA + (row * LDH + ch * 8) * 2;
            const __half* src = A + (size_t)(bm0 + row) * K + k0 + ch * 8;
            asm volatile("cp.async.cg.shared.global [%0], [%1], 16;\n" ::
                         "r"(dst), "l"(src));
        }
        constexpr int CHB = BN * CHR;
#pragma unroll
        for (int c = tid; c < CHB; c += NT) {
            int row = c / CHR, ch = c % CHR;
            int gn = bn0 + row;
            uint32_t dst = sB + (row * LDH + ch * 8) * 2;
            const __half* src = Bmat + (size_t)gn * K + k0 + ch * 8;
            int bytes = (gn < N) ? 16 : 0;
            asm volatile("cp.async.cg.shared.global [%0], [%1], 16, %2;\n" ::
                         "r"(dst), "l"(src), "r"(bytes));
        }
        asm volatile("cp.async.commit_group;\n");
    };

    float acc[MFRAG][NFRAG][4];
#pragma unroll
    for (int i = 0; i < MFRAG; i++)
#pragma unroll
        for (int j = 0; j < NFRAG; j++)
#pragma unroll
            for (int r = 0; r < 4; r++) acc[i][j][r] = 0.f;

    const int npre = (STAGES - 1 < T) ? STAGES - 1 : T;
    for (int t = 0; t < npre; t++) load_tile(t, t);

    for (int t = 0; t < T; t++) {
        asm volatile("cp.async.wait_group %0;\n" ::"n"(STAGES - 2));
        __syncthreads();
        if (t + STAGES - 1 < T) {
            load_tile((t + STAGES - 1) % STAGES, t + STAGES - 1);
        } else {
            asm volatile("cp.async.commit_group;\n");
        }
        const uint32_t sA = sbase + (t % STAGES) * ST * 2;
        const uint32_t sB = sA + A_ST * 2;
#pragma unroll
        for (int kk = 0; kk < BK; kk += 16) {
            uint32_t af[MFRAG][4];
#pragma unroll
            for (int i = 0; i < MFRAG; i++)
                ldsm_x4(af[i][0], af[i][1], af[i][2], af[i][3],
                        sA + ((wm + i * 16) * LDH + kk + a_off) * 2);
            uint32_t bf[NFRAG][2];
#pragma unroll
            for (int j = 0; j + 1 < NFRAG; j += 2)
                ldsm_x4(bf[j][0], bf[j][1], bf[j + 1][0], bf[j + 1][1],
                        sB + ((wn + j * 8) * LDH + kk + b_off) * 2);
            if (NFRAG & 1)
                ldsm_x2(bf[NFRAG - 1][0], bf[NFRAG - 1][1],
                        sB + ((wn + (NFRAG - 1) * 8) * LDH + kk + b2_off) * 2);
#pragma unroll
            for (int i = 0; i < MFRAG; i++)
#pragma unroll
                for (int j = 0; j < NFRAG; j++) MMA_F16(acc[i][j], af[i], bf[j]);
        }
    }

    if (EPI == 0) {
#pragma unroll
        for (int i = 0; i < MFRAG; i++)
#pragma unroll
            for (int j = 0; j < NFRAG; j++) {
                int n = bn0 + wn + j * 8 + gc * 2;
#pragma unroll
                for (int half_ = 0; half_ < 2; half_++) {
                    int m = bm0 + wm + i * 16 + gr + half_ * 8;
                    float v0 = acc[i][j][half_ * 2 + 0];
                    float v1 = acc[i][j][half_ * 2 + 1];
                    if (n < N)     C[(size_t)m * N + n]     = v0 + bias[n];
                    if (n + 1 < N) C[(size_t)m * N + n + 1] = v1 + bias[n + 1];
                }
            }
    } else {
        // Fused GRU update. BM=32 (batch), BN = 48 hidden-gate cols
        // interleaved (r,z,n). acc -> smem -> per-(b,j) update.
        __syncthreads();
        float* hg = (float*)smbuf;   // BM*BN floats, aliases stages (post-sync)
#pragma unroll
        for (int i = 0; i < MFRAG; i++)
#pragma unroll
            for (int j = 0; j < NFRAG; j++) {
                int m0 = wm + i * 16 + gr;
                int n0 = wn + j * 8 + gc * 2;
                hg[m0 * BN + n0]           = acc[i][j][0];
                hg[m0 * BN + n0 + 1]       = acc[i][j][1];
                hg[(m0 + 8) * BN + n0]     = acc[i][j][2];
                hg[(m0 + 8) * BN + n0 + 1] = acc[i][j][3];
            }
        __syncthreads();
        const int jbase = bn0 / 3;
        for (int it = tid; it < B_ * (BN / 3); it += NT) {
            int b = it / (BN / 3);
            int lj = it % (BN / 3);
            int jg = jbase + lj;
            float hr = hg[b * BN + 3 * lj + 0] + bias[bn0 + 3 * lj + 0];
            float hz = hg[b * BN + 3 * lj + 1] + bias[bn0 + 3 * lj + 1];
            float hn = hg[b * BN + 3 * lj + 2] + bias[bn0 + 3 * lj + 2];
            const float* xrow = xg + (size_t)(b * S_ + s) * G_ + bn0 + 3 * lj;
            float xr = xrow[0], xz = xrow[1], xn = xrow[2];
            float r = 1.f / (1.f + expf(-(xr + hr)));
            float z = 1.f / (1.f + expf(-(xz + hz)));
            float nn = tanhf(xn + r * hn);
            float h = (1.f - z) * nn + z * __half2float(h_old[b * H_ + jg]);
            __half hh = __float2half_rn(h);
            h_new[b * H_ + jg] = hh;
            hs[(size_t)(b * S_ + s) * H_ + jg] = hh;
        }
    }
}

// ---------------------------------------------------------------------------
constexpr int SMEM_A_  = 3 * (128 + 128) * 40 * 2;  //  61440 B (phase A)
constexpr int SMEM_REC = 3 * (32 + 48) * 40 * 2;    //  19200 B (recurrence)
constexpr int SMEM_C   = 4 * (128 + 256) * 40 * 2;  // 122880 B (phase C)

extern "C" void kernel_launch(void* const* d_in, const int* in_sizes, int n_in,
                              void* d_out, int out_size) {
    const int*   tgt  = (const int*)  d_in[0];
    const float* sv   = (const float*)d_in[1];
    const float* emb  = (const float*)d_in[2];
    const float* Wih  = (const float*)d_in[3];
    const float* Whh  = (const float*)d_in[4];
    const float* bih  = (const float*)d_in[5];
    const float* bhh  = (const float*)d_in[6];
    const float* Wout = (const float*)d_in[7];
    const float* bout = (const float*)d_in[8];
    float* out = (float*)d_out;

    cudaFuncSetAttribute(gemm_f16<128, 128, 32, 32, 64, 0, 3>,
                         cudaFuncAttributeMaxDynamicSharedMemorySize, SMEM_A_);
    cudaFuncSetAttribute(gemm_f16<32, 48, 32, 16, 24, 1, 3>,
                         cudaFuncAttributeMaxDynamicSharedMemorySize, SMEM_REC);
    cudaFuncSetAttribute(gemm_f16<128, 256, 32, 32, 128, 0, 4>,
                         cudaFuncAttributeMaxDynamicSharedMemorySize, SMEM_C);

    __half *p_emb, *p_hs, *p_h0, *p_h1, *p_wih, *p_whh, *p_wout;
    float *p_xg, *p_bih, *p_bhh;
    cudaGetSymbolAddress((void**)&p_emb, g_emb);
    cudaGetSymbolAddress((void**)&p_xg,  g_xg);
    cudaGetSymbolAddress((void**)&p_hs,  g_hs);
    cudaGetSymbolAddress((void**)&p_h0,  g_h0);
    cudaGetSymbolAddress((void**)&p_h1,  g_h1);
    cudaGetSymbolAddress((void**)&p_wih, g_wih);
    cudaGetSymbolAddress((void**)&p_whh, g_whh);
    cudaGetSymbolAddress((void**)&p_wout, g_wout);
    cudaGetSymbolAddress((void**)&p_bih, g_bih);
    cudaGetSymbolAddress((void**)&p_bhh, g_bhh);

    // Pre-pass: weight reorder / fp16 conversion
    prep_whh<<<2048, 256>>>(Whh);
    prep_wih_bias<<<2048, 256>>>(Wih, bih, bhh);
    prep_wout<<<4096, 256>>>(Wout);

    // Gather + h0
    gather_init_kernel<<<(M_ * EK_ + 255) / 256, 256>>>(tgt, emb, sv);

    // Phase A: x_gates (interleaved, fp32) = emb @ W_ih'^T + b_ih'  (K=320 padded)
    {
        dim3 grid(M_ / 128, (G_ + 127) / 128);
        gemm_f16<128, 128, 32, 32, 64, 0, 3><<<grid, 256, SMEM_A_>>>(
            p_emb, p_wih, p_bih, p_xg, M_, G_, EK_,
            nullptr, nullptr, nullptr, nullptr, 0);
    }

    // Phase B: 64 fused GEMM+GRU steps, 150 CTAs
    __half* hcur = p_h0;
    __half* hnext = p_h1;
    for (int s = 0; s < S_; s++) {
        dim3 grid(1, G_ / 48);  // 150 blocks
        gemm_f16<32, 48, 32, 16, 24, 1, 3><<<grid, 128, SMEM_REC>>>(
            hcur, p_whh, p_bhh, nullptr, B_, G_, H_,
            p_xg, hcur, hnext, p_hs, s);
        __half* t = hcur; hcur = hnext; hnext = t;
    }

    // Phase C: logits = hs @ W_out^T + b_out
    {
        dim3 grid(M_ / 128, (V_ + 255) / 256);  // 16 x 79, m fastest for B reuse
        gemm_f16<128, 256, 32, 32, 128, 0, 4><<<grid, 256, SMEM_C>>>(
            p_hs, p_wout, bout, out, M_, V_, H_,
            nullptr, nullptr, nullptr, nullptr, 0);
    }
}